// round 1
// baseline (speedup 1.0000x reference)
#include <cuda_runtime.h>
#include <math_constants.h>

#define NB 128
#define N 1024
#define NITERS 20
#define GROUP 16
#define NGROUPS (NB / GROUP)

// Scratch: s = (log_alpha + gumbel) / TEMP, plus row/col log-normalizers.
static __device__ float g_s[(size_t)NB * N * N];   // 512 MB
static __device__ float g_R[NB * N];
static __device__ float g_C[NB * N];

// ---------------------------------------------------------------------------
// Pass 0 (per group): compute s and zero C for this group's batches.
// Fully coalesced float4; accurate logf for the Gumbel tail (fast log would
// put O(0.1) absolute error into the extreme entries that dominate each row).
// ---------------------------------------------------------------------------
__global__ void __launch_bounds__(256) gs_init(const float* __restrict__ la,
                                               const float* __restrict__ noise,
                                               int b0) {
    const float EPS = 1e-20f;
    size_t tid = (size_t)blockIdx.x * 256 + threadIdx.x;
    size_t e = (size_t)b0 * N * N + tid * 4;
    float4 a = *reinterpret_cast<const float4*>(la + e);
    float4 u = *reinterpret_cast<const float4*>(noise + e);
    float4 s;
    s.x = (a.x - logf(EPS - logf(u.x + EPS))) * 10.0f;
    s.y = (a.y - logf(EPS - logf(u.y + EPS))) * 10.0f;
    s.z = (a.z - logf(EPS - logf(u.z + EPS))) * 10.0f;
    s.w = (a.w - logf(EPS - logf(u.w + EPS))) * 10.0f;
    *reinterpret_cast<float4*>(g_s + e) = s;
    if (tid < (size_t)GROUP * N) g_C[(size_t)b0 * N + tid] = 0.0f;
}

// ---------------------------------------------------------------------------
// Row pass: R[b,i] = logsumexp_j( s[b,i,j] - C[b,j] ).
// One warp per row; the whole 1024-element row lives in 32 registers, so the
// exact max costs nothing extra and we need exactly 1 __expf per element.
// ---------------------------------------------------------------------------
__global__ void __launch_bounds__(256) gs_row(int b0) {
    int lane = threadIdx.x & 31;
    int w = threadIdx.x >> 5;
    int rglob = b0 * N + blockIdx.x * 8 + w;     // global (batch,row) flat index
    int b = rglob >> 10;
    const float4* __restrict__ srow =
        reinterpret_cast<const float4*>(g_s + (size_t)rglob * N);
    const float4* __restrict__ crow =
        reinterpret_cast<const float4*>(g_C + (size_t)b * N);

    float x[32];
    float m = -CUDART_INF_F;
#pragma unroll
    for (int k = 0; k < 8; k++) {
        float4 sv = srow[k * 32 + lane];
        float4 cv = crow[k * 32 + lane];
        x[4 * k + 0] = sv.x - cv.x;
        x[4 * k + 1] = sv.y - cv.y;
        x[4 * k + 2] = sv.z - cv.z;
        x[4 * k + 3] = sv.w - cv.w;
        m = fmaxf(m, fmaxf(fmaxf(x[4 * k + 0], x[4 * k + 1]),
                           fmaxf(x[4 * k + 2], x[4 * k + 3])));
    }
#pragma unroll
    for (int o = 16; o; o >>= 1) m = fmaxf(m, __shfl_xor_sync(0xffffffffu, m, o));
    float ssum = 0.f;
#pragma unroll
    for (int k = 0; k < 32; k++) ssum += __expf(x[k] - m);
#pragma unroll
    for (int o = 16; o; o >>= 1) ssum += __shfl_xor_sync(0xffffffffu, ssum, o);
    if (lane == 0) g_R[rglob] = m + __logf(ssum);
}

// ---------------------------------------------------------------------------
// Col pass: C[b,j] = logsumexp_i( s[b,i,j] - R[b,i] ).
// Shift trick: s[b,i,j] - R[b,i] <= C_prev[b,j]  (since R_i >= s_ij - C_j),
// so every exp(s - R - C_prev) <= 1: no overflow, no max tracking, exactly
// one __expf/element, and cross-warp partials combine by plain addition.
// C_new = C_prev + log(sum).
// Block = (32 cols) x (8 warps over 128-row stripes), fully coalesced 128B.
// ---------------------------------------------------------------------------
__global__ void __launch_bounds__(256) gs_col(int b0) {
    int lane = threadIdx.x & 31;
    int w = threadIdx.x >> 5;
    int b = b0 + blockIdx.y;
    int j = blockIdx.x * 32 + lane;
    float cprev = g_C[(size_t)b * N + j];
    const float* __restrict__ sp = g_s + (size_t)b * N * N + j;
    const float* __restrict__ rp = g_R + (size_t)b * N;

    float sum = 0.f;
    int i0 = w * 128;
#pragma unroll 4
    for (int i = i0; i < i0 + 128; i++) {
        float x = sp[(size_t)i * N] - rp[i] - cprev;
        sum += __expf(x);
    }
    __shared__ float part[8][32];
    part[w][lane] = sum;
    __syncthreads();
    if (w == 0) {
        float t = 0.f;
#pragma unroll
        for (int k = 0; k < 8; k++) t += part[k][lane];
        g_C[(size_t)b * N + j] = cprev + __logf(t);
    }
}

// ---------------------------------------------------------------------------
// Final pass: out = exp(s - R - C).
// ---------------------------------------------------------------------------
__global__ void __launch_bounds__(256) gs_final(float* __restrict__ out, int b0) {
    size_t tid = (size_t)blockIdx.x * 256 + threadIdx.x;
    size_t e = (size_t)b0 * N * N + tid * 4;
    int row = (int)(e >> 10);
    int b = row >> 10;
    int j = (int)(e & (N - 1));
    float r = g_R[row];
    float4 c = *reinterpret_cast<const float4*>(g_C + (size_t)b * N + j);
    float4 sv = *reinterpret_cast<const float4*>(g_s + e);
    float4 o;
    o.x = __expf(sv.x - r - c.x);
    o.y = __expf(sv.y - r - c.y);
    o.z = __expf(sv.z - r - c.z);
    o.w = __expf(sv.w - r - c.w);
    *reinterpret_cast<float4*>(out + e) = o;
}

// ---------------------------------------------------------------------------
// Launch: process batches in groups of 16 (64 MB of s) so all 40 LSE passes
// of a group stay L2-resident (~126 MB L2). DRAM only sees inputs once,
// s once, and the output once.
// ---------------------------------------------------------------------------
extern "C" void kernel_launch(void* const* d_in, const int* in_sizes, int n_in,
                              void* d_out, int out_size) {
    const float* la = (const float*)d_in[0];
    const float* noise = (const float*)d_in[1];
    float* out = (float*)d_out;

    const int blk_elems = (GROUP * N * N) / (256 * 4);  // 16384 blocks (float4)
    for (int g = 0; g < NGROUPS; g++) {
        int b0 = g * GROUP;
        gs_init<<<blk_elems, 256>>>(la, noise, b0);
        for (int t = 0; t < NITERS; t++) {
            gs_row<<<(GROUP * N) / 8, 256>>>(b0);
            gs_col<<<dim3(N / 32, GROUP), 256>>>(b0);
        }
        gs_final<<<blk_elems, 256>>>(out, b0);
    }
}

// round 2
// speedup vs baseline: 1.2220x; 1.2220x over previous
#include <cuda_runtime.h>
#include <math_constants.h>

#define NB 128
#define N 1024
#define NITERS 20
#define GROUP 16
#define NGROUPS (NB / GROUP)

// Scratch: s = (log_alpha + gumbel) / TEMP, plus row/col log-normalizers.
static __device__ float g_s[(size_t)NB * N * N];   // 512 MB
static __device__ float g_R[NB * N];
static __device__ float g_C[NB * N];

// ---------------------------------------------------------------------------
// Pass 0 (per group): compute s and zero C. Coalesced float4; accurate logf
// for the Gumbel tail (fast log would corrupt the dominant extreme entries).
// ---------------------------------------------------------------------------
__global__ void __launch_bounds__(256) gs_init(const float* __restrict__ la,
                                               const float* __restrict__ noise,
                                               int b0) {
    const float EPS = 1e-20f;
    size_t tid = (size_t)blockIdx.x * 256 + threadIdx.x;
    size_t e = (size_t)b0 * N * N + tid * 4;
    float4 a = *reinterpret_cast<const float4*>(la + e);
    float4 u = *reinterpret_cast<const float4*>(noise + e);
    float4 s;
    s.x = (a.x - logf(EPS - logf(u.x + EPS))) * 10.0f;
    s.y = (a.y - logf(EPS - logf(u.y + EPS))) * 10.0f;
    s.z = (a.z - logf(EPS - logf(u.z + EPS))) * 10.0f;
    s.w = (a.w - logf(EPS - logf(u.w + EPS))) * 10.0f;
    *reinterpret_cast<float4*>(g_s + e) = s;
    if (tid < (size_t)GROUP * N) g_C[(size_t)b0 * N + tid] = 0.0f;
}

// ---------------------------------------------------------------------------
// First row pass (t=0, C=0): exact max needed since s is unbounded.
// Row lives in 32 registers per lane; one warp per row.
// ---------------------------------------------------------------------------
__global__ void __launch_bounds__(256) gs_row_first(int b0) {
    int lane = threadIdx.x & 31;
    int w = threadIdx.x >> 5;
    int rglob = b0 * N + blockIdx.x * 8 + w;
    const float4* __restrict__ srow =
        reinterpret_cast<const float4*>(g_s + (size_t)rglob * N);

    float x[32];
    float m = -CUDART_INF_F;
#pragma unroll
    for (int k = 0; k < 8; k++) {
        float4 sv = srow[k * 32 + lane];
        x[4 * k + 0] = sv.x; x[4 * k + 1] = sv.y;
        x[4 * k + 2] = sv.z; x[4 * k + 3] = sv.w;
        m = fmaxf(m, fmaxf(fmaxf(sv.x, sv.y), fmaxf(sv.z, sv.w)));
    }
#pragma unroll
    for (int o = 16; o; o >>= 1) m = fmaxf(m, __shfl_xor_sync(0xffffffffu, m, o));
    float ssum = 0.f;
#pragma unroll
    for (int k = 0; k < 32; k++) ssum += __expf(x[k] - m);
#pragma unroll
    for (int o = 16; o; o >>= 1) ssum += __shfl_xor_sync(0xffffffffu, ssum, o);
    if (lane == 0) g_R[rglob] = m + __logf(ssum);
}

// ---------------------------------------------------------------------------
// Row pass, t>=1, shift trick: since C_j = LSE_i(s_ij - R_i) >= s_ij - R_i,
// every exp(s - C - R_prev) <= 1: no max tracking, pure streaming reduction,
// low register count -> full occupancy.  R_new = R_prev + log(sum).
// ---------------------------------------------------------------------------
__global__ void __launch_bounds__(256) gs_row(int b0) {
    int lane = threadIdx.x & 31;
    int w = threadIdx.x >> 5;
    int rglob = b0 * N + blockIdx.x * 8 + w;
    int b = rglob >> 10;
    const float4* __restrict__ srow =
        reinterpret_cast<const float4*>(g_s + (size_t)rglob * N);
    const float4* __restrict__ crow =
        reinterpret_cast<const float4*>(g_C + (size_t)b * N);
    float rprev = g_R[rglob];

    float a0 = 0.f, a1 = 0.f;
#pragma unroll
    for (int k = 0; k < 8; k += 2) {
        float4 s0 = srow[k * 32 + lane];
        float4 c0 = crow[k * 32 + lane];
        float4 s1 = srow[(k + 1) * 32 + lane];
        float4 c1 = crow[(k + 1) * 32 + lane];
        a0 += __expf(s0.x - c0.x - rprev) + __expf(s0.y - c0.y - rprev)
            + __expf(s0.z - c0.z - rprev) + __expf(s0.w - c0.w - rprev);
        a1 += __expf(s1.x - c1.x - rprev) + __expf(s1.y - c1.y - rprev)
            + __expf(s1.z - c1.z - rprev) + __expf(s1.w - c1.w - rprev);
    }
    float ssum = a0 + a1;
#pragma unroll
    for (int o = 16; o; o >>= 1) ssum += __shfl_xor_sync(0xffffffffu, ssum, o);
    if (lane == 0) g_R[rglob] = rprev + __logf(ssum);
}

// ---------------------------------------------------------------------------
// Col pass, shift trick (s_ij - R_i <= C_prev_j always): partials combine by
// plain addition.  Block = 1024 threads: 32 warps x 32-row stripes, 32 cols
// per block, fully coalesced 128B lines.  C_new = C_prev + log(sum).
// ---------------------------------------------------------------------------
__global__ void __launch_bounds__(1024) gs_col(int b0) {
    int lane = threadIdx.x & 31;
    int w = threadIdx.x >> 5;
    int b = b0 + blockIdx.y;
    int j = blockIdx.x * 32 + lane;
    float cprev = g_C[(size_t)b * N + j];
    const float* __restrict__ sp = g_s + (size_t)b * N * N + j;
    const float* __restrict__ rp = g_R + (size_t)b * N;

    int i0 = w * 32;
    float acc0 = 0.f, acc1 = 0.f, acc2 = 0.f, acc3 = 0.f;
#pragma unroll
    for (int i = 0; i < 32; i += 4) {
        acc0 += __expf(sp[(size_t)(i0 + i + 0) * N] - rp[i0 + i + 0] - cprev);
        acc1 += __expf(sp[(size_t)(i0 + i + 1) * N] - rp[i0 + i + 1] - cprev);
        acc2 += __expf(sp[(size_t)(i0 + i + 2) * N] - rp[i0 + i + 2] - cprev);
        acc3 += __expf(sp[(size_t)(i0 + i + 3) * N] - rp[i0 + i + 3] - cprev);
    }
    __shared__ float part[32][33];
    part[w][lane] = (acc0 + acc1) + (acc2 + acc3);
    __syncthreads();
    if (w == 0) {
        float t = 0.f;
#pragma unroll
        for (int k = 0; k < 32; k++) t += part[k][lane];
        g_C[(size_t)b * N + j] = cprev + __logf(t);
    }
}

// ---------------------------------------------------------------------------
// Final pass: out = exp(s - R - C).  Reads s L2-hot from the last col pass.
// ---------------------------------------------------------------------------
__global__ void __launch_bounds__(256) gs_final(float* __restrict__ out, int b0) {
    size_t tid = (size_t)blockIdx.x * 256 + threadIdx.x;
    size_t e = (size_t)b0 * N * N + tid * 4;
    int row = (int)(e >> 10);
    int b = row >> 10;
    int j = (int)(e & (N - 1));
    float r = g_R[row];
    float4 c = *reinterpret_cast<const float4*>(g_C + (size_t)b * N + j);
    float4 sv = *reinterpret_cast<const float4*>(g_s + e);
    float4 o;
    o.x = __expf(sv.x - r - c.x);
    o.y = __expf(sv.y - r - c.y);
    o.z = __expf(sv.z - r - c.z);
    o.w = __expf(sv.w - r - c.w);
    *reinterpret_cast<float4*>(out + e) = o;
}

// ---------------------------------------------------------------------------
// Groups of 16 batches (64 MB of s) keep all 40 LSE passes L2-resident.
// ---------------------------------------------------------------------------
extern "C" void kernel_launch(void* const* d_in, const int* in_sizes, int n_in,
                              void* d_out, int out_size) {
    const float* la = (const float*)d_in[0];
    const float* noise = (const float*)d_in[1];
    float* out = (float*)d_out;

    const int blk_elems = (GROUP * N * N) / (256 * 4);
    for (int g = 0; g < NGROUPS; g++) {
        int b0 = g * GROUP;
        gs_init<<<blk_elems, 256>>>(la, noise, b0);
        gs_row_first<<<(GROUP * N) / 8, 256>>>(b0);
        gs_col<<<dim3(N / 32, GROUP), 1024>>>(b0);
        for (int t = 1; t < NITERS; t++) {
            gs_row<<<(GROUP * N) / 8, 256>>>(b0);
            gs_col<<<dim3(N / 32, GROUP), 1024>>>(b0);
        }
        gs_final<<<blk_elems, 256>>>(out, b0);
    }
}